// round 3
// baseline (speedup 1.0000x reference)
#include <cuda_runtime.h>

#define NNODES 50000
#define NEDGES 800000
#define HID 128

__device__ float g_agg[(size_t)NNODES * HID];
__device__ float g_h[(size_t)NNODES * HID];
__device__ float g_colsum[HID];
__device__ float g_b1adj[HID];
__device__ int g_is64;  // 1 if edge_index is int64, 0 if int32

// ---------------------------------------------------------------------------
// Detect edge_index dtype. int64 little-endian values < 2^31 have zero high
// words at every odd int32 position; random int32 indices do not.
// ---------------------------------------------------------------------------
__global__ void detect_kernel(const int* __restrict__ ei32) {
    __shared__ int nz;
    if (threadIdx.x == 0) nz = 0;
    __syncthreads();
    int cnt = 0;
    for (int i = threadIdx.x; i < 1024; i += blockDim.x)
        if (ei32[2 * i + 1] != 0) cnt++;
    atomicAdd(&nz, cnt);
    __syncthreads();
    if (threadIdx.x == 0) g_is64 = (nz == 0) ? 1 : 0;
}

__global__ void zero_kernel() {
    size_t total = (size_t)NNODES * HID;
    for (size_t i = (size_t)blockIdx.x * blockDim.x + threadIdx.x; i < total;
         i += (size_t)gridDim.x * blockDim.x)
        g_agg[i] = 0.0f;
    if (blockIdx.x == 0 && threadIdx.x < HID) g_colsum[threadIdx.x] = 0.0f;
}

// ---------------------------------------------------------------------------
// Scatter-add edge rows into g_agg[receiver]; fused edge_attr passthrough.
// 1 warp per edge, float4 per lane.
// ---------------------------------------------------------------------------
__global__ void __launch_bounds__(256) scatter_kernel(
    const float* __restrict__ edge_attr,
    const void* __restrict__ edge_index,
    float* __restrict__ out_edge_attr) {
    int e = blockIdx.x * 8 + (threadIdx.x >> 5);
    if (e >= NEDGES) return;
    int lane = threadIdx.x & 31;

    long long recv;
    if (g_is64)
        recv = ((const long long*)edge_index)[(size_t)NEDGES + e];
    else
        recv = ((const int*)edge_index)[(size_t)NEDGES + e];
    if (recv < 0 || recv >= NNODES) return;  // safety clamp

    float4 v = ((const float4*)(edge_attr + (size_t)e * HID))[lane];
    if (out_edge_attr)
        ((float4*)(out_edge_attr + (size_t)e * HID))[lane] = v;

    float* dst = g_agg + (size_t)recv * HID + lane * 4;
    atomicAdd(dst + 0, v.x);
    atomicAdd(dst + 1, v.y);
    atomicAdd(dst + 2, v.z);
    atomicAdd(dst + 3, v.w);
}

__global__ void eidx_copy_kernel(const void* __restrict__ ei,
                                 float* __restrict__ out) {
    int total = 2 * NEDGES;
    for (int i = blockIdx.x * blockDim.x + threadIdx.x; i < total;
         i += gridDim.x * blockDim.x) {
        long long v;
        if (g_is64)
            v = ((const long long*)ei)[i];
        else
            v = ((const int*)ei)[i];
        out[i] = (float)v;
    }
}

__global__ void colsum_kernel() {
    int j = threadIdx.x;
    float s = 0.0f;
    for (int r = blockIdx.x; r < NNODES; r += gridDim.x)
        s += g_agg[(size_t)r * HID + j];
    atomicAdd(&g_colsum[j], s);
}

// b1'[j] = b1[j] - (1/N) * sum_c colsum[c] * W1[128+c][j]
__global__ void b1adj_kernel(const float* __restrict__ W1,
                             const float* __restrict__ b1) {
    int j = threadIdx.x;
    float acc = 0.0f;
#pragma unroll 8
    for (int c = 0; c < HID; c++)
        acc = fmaf(g_colsum[c], W1[(size_t)(HID + c) * HID + j], acc);
    g_b1adj[j] = b1[j] - acc * (1.0f / (float)NNODES);
}

// ---------------------------------------------------------------------------
// C[M,128] = act(A[M,K] @ B[K,128] + bias); BM=BN=128, BK=16, 256 thr, 8x8/thr
// CONCAT: logical A = [A0 | A1], split at k=128.
// As padded to 132 cols: row stride 528B = 33*16 -> every &As[k][8*ty] is
// 16B-aligned (129 made odd-k rows 4B-aligned -> LDS.128 misaligned trap).
// ---------------------------------------------------------------------------
template <int K_TOTAL, bool CONCAT, bool RELU>
__global__ void __launch_bounds__(256) gemm_kernel(
    const float* __restrict__ A0, const float* __restrict__ A1,
    const float* __restrict__ B, const float* __restrict__ bias,
    float* __restrict__ C) {
    __shared__ float As[16][132];
    __shared__ float Bs[16][128];

    const int block_m = blockIdx.x * 128;
    const int t = threadIdx.x;
    const int tx = t & 15;
    const int ty = t >> 4;

    const int arow = t >> 2;
    const int acol = (t & 3) * 4;
    const int brow = t >> 5;
    const int bcol = (t & 31) * 4;

    float acc[8][8];
#pragma unroll
    for (int i = 0; i < 8; i++)
#pragma unroll
        for (int j = 0; j < 8; j++) acc[i][j] = 0.0f;

    for (int k0 = 0; k0 < K_TOTAL; k0 += 16) {
#pragma unroll
        for (int half = 0; half < 2; half++) {
            int m = arow + half * 64;
            int gm = block_m + m;
            float4 v = make_float4(0.f, 0.f, 0.f, 0.f);
            if (gm < NNODES) {
                int k = k0 + acol;
                const float* src;
                if (CONCAT)
                    src = (k < HID) ? (A0 + (size_t)gm * HID + k)
                                    : (A1 + (size_t)gm * HID + (k - HID));
                else
                    src = A0 + (size_t)gm * K_TOTAL + k;
                v = *(const float4*)src;
            }
            As[acol + 0][m] = v.x;
            As[acol + 1][m] = v.y;
            As[acol + 2][m] = v.z;
            As[acol + 3][m] = v.w;
        }
#pragma unroll
        for (int half = 0; half < 2; half++) {
            int kr = brow + half * 8;
            *(float4*)&Bs[kr][bcol] =
                *(const float4*)(B + (size_t)(k0 + kr) * HID + bcol);
        }
        __syncthreads();

#pragma unroll
        for (int k = 0; k < 16; k++) {
            float a[8], b[8];
#pragma unroll
            for (int i = 0; i < 8; i += 4)
                *(float4*)&a[i] = *(const float4*)&As[k][ty * 8 + i];
#pragma unroll
            for (int j = 0; j < 8; j += 4)
                *(float4*)&b[j] = *(const float4*)&Bs[k][tx * 8 + j];
#pragma unroll
            for (int i = 0; i < 8; i++)
#pragma unroll
                for (int j = 0; j < 8; j++)
                    acc[i][j] = fmaf(a[i], b[j], acc[i][j]);
        }
        __syncthreads();
    }

#pragma unroll
    for (int i = 0; i < 8; i++) {
        int gm = block_m + ty * 8 + i;
        if (gm >= NNODES) continue;
#pragma unroll
        for (int j = 0; j < 8; j += 4) {
            int n = tx * 8 + j;
            float4 v;
            v.x = acc[i][j + 0] + bias[n + 0];
            v.y = acc[i][j + 1] + bias[n + 1];
            v.z = acc[i][j + 2] + bias[n + 2];
            v.w = acc[i][j + 3] + bias[n + 3];
            if (RELU) {
                v.x = fmaxf(v.x, 0.f);
                v.y = fmaxf(v.y, 0.f);
                v.z = fmaxf(v.z, 0.f);
                v.w = fmaxf(v.w, 0.f);
            }
            *(float4*)(C + (size_t)gm * HID + n) = v;
        }
    }
}

extern "C" void kernel_launch(void* const* d_in, const int* in_sizes, int n_in,
                              void* d_out, int out_size) {
    const float* node_attr = (const float*)d_in[0];
    const void* edge_index = d_in[1];
    const float* edge_attr = (const float*)d_in[2];
    const float* W1 = (const float*)d_in[3];
    const float* b1 = (const float*)d_in[4];
    const float* W2 = (const float*)d_in[5];
    const float* b2 = (const float*)d_in[6];
    float* out = (float*)d_out;

    float *s_agg, *s_h, *s_b1adj;
    cudaGetSymbolAddress((void**)&s_agg, g_agg);
    cudaGetSymbolAddress((void**)&s_h, g_h);
    cudaGetSymbolAddress((void**)&s_b1adj, g_b1adj);

    const size_t off_ei = (size_t)NNODES * HID;            // 6,400,000
    const size_t off_ea = off_ei + 2ULL * NEDGES;          // 8,000,000
    const size_t full = off_ea + (size_t)NEDGES * HID;     // 110,400,000
    const bool want_ei = (size_t)out_size >= off_ea;
    const bool want_ea = (size_t)out_size >= full;

    detect_kernel<<<1, 256>>>((const int*)edge_index);
    zero_kernel<<<1024, 256>>>();
    scatter_kernel<<<(NEDGES + 7) / 8, 256>>>(
        edge_attr, edge_index, want_ea ? (out + off_ea) : nullptr);
    if (want_ei) eidx_copy_kernel<<<1024, 256>>>(edge_index, out + off_ei);
    colsum_kernel<<<256, 128>>>();
    b1adj_kernel<<<1, 128>>>(W1, b1);

    const int mblocks = (NNODES + 127) / 128;  // 391
    gemm_kernel<256, true, true><<<mblocks, 256>>>(node_attr, s_agg, W1,
                                                   s_b1adj, s_h);
    gemm_kernel<128, false, false><<<mblocks, 256>>>(s_h, nullptr, W2, b2,
                                                     out);
}

// round 4
// speedup vs baseline: 1.2966x; 1.2966x over previous
#include <cuda_runtime.h>

#define NNODES 50000
#define NEDGES 800000
#define HID 128

__device__ float g_agg[(size_t)NNODES * HID];
__device__ float g_h[(size_t)NNODES * HID];
__device__ float g_colsum[HID];
__device__ float g_b1adj[HID];
__device__ int g_is64;  // 1 if edge_index is int64, 0 if int32

// ---------------------------------------------------------------------------
// Detect edge_index dtype. int64 little-endian values < 2^31 have zero high
// words at every odd int32 position; random int32 indices do not.
// ---------------------------------------------------------------------------
__global__ void detect_kernel(const int* __restrict__ ei32) {
    __shared__ int nz;
    if (threadIdx.x == 0) nz = 0;
    __syncthreads();
    int cnt = 0;
    for (int i = threadIdx.x; i < 1024; i += blockDim.x)
        if (ei32[2 * i + 1] != 0) cnt++;
    atomicAdd(&nz, cnt);
    __syncthreads();
    if (threadIdx.x == 0) g_is64 = (nz == 0) ? 1 : 0;
}

__global__ void zero_kernel() {
    size_t total = (size_t)NNODES * HID;
    for (size_t i = (size_t)blockIdx.x * blockDim.x + threadIdx.x; i < total;
         i += (size_t)gridDim.x * blockDim.x)
        g_agg[i] = 0.0f;
    if (blockIdx.x == 0 && threadIdx.x < HID) g_colsum[threadIdx.x] = 0.0f;
}

// ---------------------------------------------------------------------------
// Scatter-add edge rows into g_agg[receiver]; fused edge_attr passthrough.
// 1 warp per edge, float4 per lane, ONE red.global.add.v4.f32 per lane
// (4x fewer atomic ops than scalar atomicAdd).
// ---------------------------------------------------------------------------
__global__ void __launch_bounds__(256) scatter_kernel(
    const float* __restrict__ edge_attr,
    const void* __restrict__ edge_index,
    float* __restrict__ out_edge_attr) {
    int e = blockIdx.x * 8 + (threadIdx.x >> 5);
    if (e >= NEDGES) return;
    int lane = threadIdx.x & 31;

    long long recv;
    if (g_is64)
        recv = ((const long long*)edge_index)[(size_t)NEDGES + e];
    else
        recv = ((const int*)edge_index)[(size_t)NEDGES + e];
    if (recv < 0 || recv >= NNODES) return;  // safety clamp

    float4 v = ((const float4*)(edge_attr + (size_t)e * HID))[lane];
    if (out_edge_attr)
        ((float4*)(out_edge_attr + (size_t)e * HID))[lane] = v;

    float* dst = g_agg + (size_t)recv * HID + lane * 4;  // 16B-aligned
    asm volatile("red.global.add.v4.f32 [%0], {%1, %2, %3, %4};"
                 :: "l"(dst), "f"(v.x), "f"(v.y), "f"(v.z), "f"(v.w)
                 : "memory");
}

__global__ void eidx_copy_kernel(const void* __restrict__ ei,
                                 float* __restrict__ out) {
    int total = 2 * NEDGES;
    for (int i = blockIdx.x * blockDim.x + threadIdx.x; i < total;
         i += gridDim.x * blockDim.x) {
        long long v;
        if (g_is64)
            v = ((const long long*)ei)[i];
        else
            v = ((const int*)ei)[i];
        out[i] = (float)v;
    }
}

__global__ void colsum_kernel() {
    int j = threadIdx.x;
    float s = 0.0f;
    for (int r = blockIdx.x; r < NNODES; r += gridDim.x)
        s += g_agg[(size_t)r * HID + j];
    atomicAdd(&g_colsum[j], s);
}

// b1'[j] = b1[j] - (1/N) * sum_c colsum[c] * W1[128+c][j]
__global__ void b1adj_kernel(const float* __restrict__ W1,
                             const float* __restrict__ b1) {
    int j = threadIdx.x;
    float acc = 0.0f;
#pragma unroll 8
    for (int c = 0; c < HID; c++)
        acc = fmaf(g_colsum[c], W1[(size_t)(HID + c) * HID + j], acc);
    g_b1adj[j] = b1[j] - acc * (1.0f / (float)NNODES);
}

// ---------------------------------------------------------------------------
// C[M,128] = act(A[M,K] @ B[K,128] + bias); BM=BN=128, BK=16, 256 thr, 8x8/thr
// CONCAT: logical A = [A0 | A1], split at k=128.
// As padded to 132 cols: row stride 528B = 33*16 -> 16B-aligned LDS.128.
// ---------------------------------------------------------------------------
template <int K_TOTAL, bool CONCAT, bool RELU>
__global__ void __launch_bounds__(256) gemm_kernel(
    const float* __restrict__ A0, const float* __restrict__ A1,
    const float* __restrict__ B, const float* __restrict__ bias,
    float* __restrict__ C) {
    __shared__ float As[16][132];
    __shared__ float Bs[16][128];

    const int block_m = blockIdx.x * 128;
    const int t = threadIdx.x;
    const int tx = t & 15;
    const int ty = t >> 4;

    const int arow = t >> 2;
    const int acol = (t & 3) * 4;
    const int brow = t >> 5;
    const int bcol = (t & 31) * 4;

    float acc[8][8];
#pragma unroll
    for (int i = 0; i < 8; i++)
#pragma unroll
        for (int j = 0; j < 8; j++) acc[i][j] = 0.0f;

    for (int k0 = 0; k0 < K_TOTAL; k0 += 16) {
#pragma unroll
        for (int half = 0; half < 2; half++) {
            int m = arow + half * 64;
            int gm = block_m + m;
            float4 v = make_float4(0.f, 0.f, 0.f, 0.f);
            if (gm < NNODES) {
                int k = k0 + acol;
                const float* src;
                if (CONCAT)
                    src = (k < HID) ? (A0 + (size_t)gm * HID + k)
                                    : (A1 + (size_t)gm * HID + (k - HID));
                else
                    src = A0 + (size_t)gm * K_TOTAL + k;
                v = *(const float4*)src;
            }
            As[acol + 0][m] = v.x;
            As[acol + 1][m] = v.y;
            As[acol + 2][m] = v.z;
            As[acol + 3][m] = v.w;
        }
#pragma unroll
        for (int half = 0; half < 2; half++) {
            int kr = brow + half * 8;
            *(float4*)&Bs[kr][bcol] =
                *(const float4*)(B + (size_t)(k0 + kr) * HID + bcol);
        }
        __syncthreads();

#pragma unroll
        for (int k = 0; k < 16; k++) {
            float a[8], b[8];
#pragma unroll
            for (int i = 0; i < 8; i += 4)
                *(float4*)&a[i] = *(const float4*)&As[k][ty * 8 + i];
#pragma unroll
            for (int j = 0; j < 8; j += 4)
                *(float4*)&b[j] = *(const float4*)&Bs[k][tx * 8 + j];
#pragma unroll
            for (int i = 0; i < 8; i++)
#pragma unroll
                for (int j = 0; j < 8; j++)
                    acc[i][j] = fmaf(a[i], b[j], acc[i][j]);
        }
        __syncthreads();
    }

#pragma unroll
    for (int i = 0; i < 8; i++) {
        int gm = block_m + ty * 8 + i;
        if (gm >= NNODES) continue;
#pragma unroll
        for (int j = 0; j < 8; j += 4) {
            int n = tx * 8 + j;
            float4 v;
            v.x = acc[i][j + 0] + bias[n + 0];
            v.y = acc[i][j + 1] + bias[n + 1];
            v.z = acc[i][j + 2] + bias[n + 2];
            v.w = acc[i][j + 3] + bias[n + 3];
            if (RELU) {
                v.x = fmaxf(v.x, 0.f);
                v.y = fmaxf(v.y, 0.f);
                v.z = fmaxf(v.z, 0.f);
                v.w = fmaxf(v.w, 0.f);
            }
            *(float4*)(C + (size_t)gm * HID + n) = v;
        }
    }
}

extern "C" void kernel_launch(void* const* d_in, const int* in_sizes, int n_in,
                              void* d_out, int out_size) {
    const float* node_attr = (const float*)d_in[0];
    const void* edge_index = d_in[1];
    const float* edge_attr = (const float*)d_in[2];
    const float* W1 = (const float*)d_in[3];
    const float* b1 = (const float*)d_in[4];
    const float* W2 = (const float*)d_in[5];
    const float* b2 = (const float*)d_in[6];
    float* out = (float*)d_out;

    float *s_agg, *s_h, *s_b1adj;
    cudaGetSymbolAddress((void**)&s_agg, g_agg);
    cudaGetSymbolAddress((void**)&s_h, g_h);
    cudaGetSymbolAddress((void**)&s_b1adj, g_b1adj);

    const size_t off_ei = (size_t)NNODES * HID;            // 6,400,000
    const size_t off_ea = off_ei + 2ULL * NEDGES;          // 8,000,000
    const size_t full = off_ea + (size_t)NEDGES * HID;     // 110,400,000
    const bool want_ei = (size_t)out_size >= off_ea;
    const bool want_ea = (size_t)out_size >= full;

    detect_kernel<<<1, 256>>>((const int*)edge_index);
    zero_kernel<<<1024, 256>>>();
    scatter_kernel<<<(NEDGES + 7) / 8, 256>>>(
        edge_attr, edge_index, want_ea ? (out + off_ea) : nullptr);
    if (want_ei) eidx_copy_kernel<<<1024, 256>>>(edge_index, out + off_ei);
    colsum_kernel<<<256, 128>>>();
    b1adj_kernel<<<1, 128>>>(W1, b1);

    const int mblocks = (NNODES + 127) / 128;  // 391
    gemm_kernel<256, true, true><<<mblocks, 256>>>(node_attr, s_agg, W1,
                                                   s_b1adj, s_h);
    gemm_kernel<128, false, false><<<mblocks, 256>>>(s_h, nullptr, W2, b2,
                                                     out);
}

// round 5
// speedup vs baseline: 1.5209x; 1.1730x over previous
#include <cuda_runtime.h>
#include <cstdint>

#define NNODES 50000
#define NEDGES 800000
#define HID 128

__device__ float g_agg[(size_t)NNODES * HID];
__device__ float g_h[(size_t)NNODES * HID];
__device__ float g_colsum[HID];
__device__ float g_b1adj[HID];
__device__ int g_is64;  // 1 if edge_index is int64, 0 if int32

// ---------------------------------------------------------------------------
// Detect edge_index dtype (int64 values < 2^31 have zero odd int32 words).
// ---------------------------------------------------------------------------
__global__ void detect_kernel(const int* __restrict__ ei32) {
    __shared__ int nz;
    if (threadIdx.x == 0) nz = 0;
    __syncthreads();
    int cnt = 0;
    for (int i = threadIdx.x; i < 1024; i += blockDim.x)
        if (ei32[2 * i + 1] != 0) cnt++;
    atomicAdd(&nz, cnt);
    __syncthreads();
    if (threadIdx.x == 0) g_is64 = (nz == 0) ? 1 : 0;
}

__global__ void zero_kernel() {
    size_t total = (size_t)NNODES * HID;
    for (size_t i = (size_t)blockIdx.x * blockDim.x + threadIdx.x; i < total;
         i += (size_t)gridDim.x * blockDim.x)
        g_agg[i] = 0.0f;
    if (blockIdx.x == 0 && threadIdx.x < HID) g_colsum[threadIdx.x] = 0.0f;
}

// ---------------------------------------------------------------------------
// Scatter-add edge rows into g_agg[receiver]; fused edge_attr passthrough.
// 1 warp per edge, one red.global.add.v4.f32 per lane.
// ---------------------------------------------------------------------------
__global__ void __launch_bounds__(256) scatter_kernel(
    const float* __restrict__ edge_attr,
    const void* __restrict__ edge_index,
    float* __restrict__ out_edge_attr) {
    int e = blockIdx.x * 8 + (threadIdx.x >> 5);
    if (e >= NEDGES) return;
    int lane = threadIdx.x & 31;

    long long recv;
    if (g_is64)
        recv = ((const long long*)edge_index)[(size_t)NEDGES + e];
    else
        recv = ((const int*)edge_index)[(size_t)NEDGES + e];
    if (recv < 0 || recv >= NNODES) return;

    float4 v = ((const float4*)(edge_attr + (size_t)e * HID))[lane];
    if (out_edge_attr)
        ((float4*)(out_edge_attr + (size_t)e * HID))[lane] = v;

    float* dst = g_agg + (size_t)recv * HID + lane * 4;
    asm volatile("red.global.add.v4.f32 [%0], {%1, %2, %3, %4};"
                 :: "l"(dst), "f"(v.x), "f"(v.y), "f"(v.z), "f"(v.w)
                 : "memory");
}

__global__ void eidx_copy_kernel(const void* __restrict__ ei,
                                 float* __restrict__ out) {
    int total = 2 * NEDGES;
    for (int i = blockIdx.x * blockDim.x + threadIdx.x; i < total;
         i += gridDim.x * blockDim.x) {
        long long v;
        if (g_is64)
            v = ((const long long*)ei)[i];
        else
            v = ((const int*)ei)[i];
        out[i] = (float)v;
    }
}

__global__ void colsum_kernel() {
    int j = threadIdx.x;
    float s = 0.0f;
    for (int r = blockIdx.x; r < NNODES; r += gridDim.x)
        s += g_agg[(size_t)r * HID + j];
    atomicAdd(&g_colsum[j], s);
}

// b1'[j] = b1[j] - (1/N) * sum_c colsum[c] * W1[128+c][j]
__global__ void b1adj_kernel(const float* __restrict__ W1,
                             const float* __restrict__ b1) {
    int j = threadIdx.x;
    float acc = 0.0f;
#pragma unroll 8
    for (int c = 0; c < HID; c++)
        acc = fmaf(g_colsum[c], W1[(size_t)(HID + c) * HID + j], acc);
    g_b1adj[j] = b1[j] - acc * (1.0f / (float)NNODES);
}

// ---------------------------------------------------------------------------
// Tensor-core GEMM: C[M,128] = act(A[M,K] @ B[K,128] + bias), tf32 mma.sync.
// BM=BN=128, BK=32, 256 thr = 8 warps in 2x4 grid of 64x32 warp tiles.
// Each warp tile = 4x4 m16n8k8 fragments. tf32 cvt applied at smem store.
// As[128][36]: a-frag banks (4g+j) distinct; Bs[32][132]: b-frag banks
// (4j+g) distinct -> conflict-free fragment LDS.
// ---------------------------------------------------------------------------
__device__ __forceinline__ float f2tf(float x) {
    uint32_t r;
    asm("cvt.rna.tf32.f32 %0, %1;" : "=r"(r) : "f"(x));
    return __uint_as_float(r);
}

__device__ __forceinline__ void mma_tf32(float* c, const uint32_t* a,
                                         const uint32_t* b) {
    asm volatile(
        "mma.sync.aligned.m16n8k8.row.col.f32.tf32.tf32.f32 "
        "{%0,%1,%2,%3}, {%4,%5,%6,%7}, {%8,%9}, {%0,%1,%2,%3};"
        : "+f"(c[0]), "+f"(c[1]), "+f"(c[2]), "+f"(c[3])
        : "r"(a[0]), "r"(a[1]), "r"(a[2]), "r"(a[3]), "r"(b[0]), "r"(b[1]));
}

template <int K_TOTAL, bool CONCAT, bool RELU>
__global__ void __launch_bounds__(256) gemm_tc_kernel(
    const float* __restrict__ A0, const float* __restrict__ A1,
    const float* __restrict__ B, const float* __restrict__ bias,
    float* __restrict__ C) {
    __shared__ float As[128][36];
    __shared__ float Bs[32][132];

    const int t = threadIdx.x;
    const int w = t >> 5, lane = t & 31;
    const int wm = w >> 2, wn = w & 3;   // 2 x 4 warp grid
    const int g = lane >> 2, j = lane & 3;
    const int block_m = blockIdx.x * 128;

    float acc[4][4][4] = {};

    for (int kb = 0; kb < K_TOTAL / 32; kb++) {
        const int kbase = kb * 32;
        // ---- load A tile [128 x 32] (tf32-rounded) ----
#pragma unroll
        for (int i = 0; i < 4; i++) {
            int idx = i * 256 + t;
            int row = idx >> 3;
            int c4 = (idx & 7) * 4;
            int gm = block_m + row;
            float4 v = make_float4(0.f, 0.f, 0.f, 0.f);
            if (gm < NNODES) {
                int k = kbase + c4;
                const float* src;
                if (CONCAT)
                    src = (k < HID) ? (A0 + (size_t)gm * HID + k)
                                    : (A1 + (size_t)gm * HID + (k - HID));
                else
                    src = A0 + (size_t)gm * K_TOTAL + k;
                v = *(const float4*)src;
            }
            float4 tv = make_float4(f2tf(v.x), f2tf(v.y), f2tf(v.z), f2tf(v.w));
            *(float4*)&As[row][c4] = tv;
        }
        // ---- load B tile [32 x 128] (tf32-rounded) ----
#pragma unroll
        for (int i = 0; i < 4; i++) {
            int idx = i * 256 + t;
            int kr = idx >> 5;
            int c4 = (idx & 31) * 4;
            float4 v = *(const float4*)(B + (size_t)(kbase + kr) * HID + c4);
            float4 tv = make_float4(f2tf(v.x), f2tf(v.y), f2tf(v.z), f2tf(v.w));
            *(float4*)&Bs[kr][c4] = tv;
        }
        __syncthreads();

#pragma unroll
        for (int kk = 0; kk < 4; kk++) {
            const int k0 = kk * 8;
            uint32_t bf[4][2];
#pragma unroll
            for (int nt = 0; nt < 4; nt++) {
                int n0 = wn * 32 + nt * 8 + g;
                bf[nt][0] = __float_as_uint(Bs[k0 + j][n0]);
                bf[nt][1] = __float_as_uint(Bs[k0 + j + 4][n0]);
            }
#pragma unroll
            for (int mt = 0; mt < 4; mt++) {
                int m0 = wm * 64 + mt * 16;
                uint32_t af[4];
                af[0] = __float_as_uint(As[m0 + g][k0 + j]);
                af[1] = __float_as_uint(As[m0 + g + 8][k0 + j]);
                af[2] = __float_as_uint(As[m0 + g][k0 + j + 4]);
                af[3] = __float_as_uint(As[m0 + g + 8][k0 + j + 4]);
#pragma unroll
                for (int nt = 0; nt < 4; nt++) mma_tf32(acc[mt][nt], af, bf[nt]);
            }
        }
        __syncthreads();
    }

    // ---- epilogue: bias (+relu), float2 stores ----
#pragma unroll
    for (int mt = 0; mt < 4; mt++) {
#pragma unroll
        for (int half = 0; half < 2; half++) {
            int gm = block_m + wm * 64 + mt * 16 + g + half * 8;
            if (gm >= NNODES) continue;
#pragma unroll
            for (int nt = 0; nt < 4; nt++) {
                int n = wn * 32 + nt * 8 + 2 * j;
                float2 v;
                v.x = acc[mt][nt][half * 2 + 0] + bias[n + 0];
                v.y = acc[mt][nt][half * 2 + 1] + bias[n + 1];
                if (RELU) {
                    v.x = fmaxf(v.x, 0.f);
                    v.y = fmaxf(v.y, 0.f);
                }
                *(float2*)(C + (size_t)gm * HID + n) = v;
            }
        }
    }
}

extern "C" void kernel_launch(void* const* d_in, const int* in_sizes, int n_in,
                              void* d_out, int out_size) {
    const float* node_attr = (const float*)d_in[0];
    const void* edge_index = d_in[1];
    const float* edge_attr = (const float*)d_in[2];
    const float* W1 = (const float*)d_in[3];
    const float* b1 = (const float*)d_in[4];
    const float* W2 = (const float*)d_in[5];
    const float* b2 = (const float*)d_in[6];
    float* out = (float*)d_out;

    float *s_agg, *s_h, *s_b1adj;
    cudaGetSymbolAddress((void**)&s_agg, g_agg);
    cudaGetSymbolAddress((void**)&s_h, g_h);
    cudaGetSymbolAddress((void**)&s_b1adj, g_b1adj);

    const size_t off_ei = (size_t)NNODES * HID;            // 6,400,000
    const size_t off_ea = off_ei + 2ULL * NEDGES;          // 8,000,000
    const size_t full = off_ea + (size_t)NEDGES * HID;     // 110,400,000
    const bool want_ei = (size_t)out_size >= off_ea;
    const bool want_ea = (size_t)out_size >= full;

    detect_kernel<<<1, 256>>>((const int*)edge_index);
    zero_kernel<<<1024, 256>>>();
    scatter_kernel<<<(NEDGES + 7) / 8, 256>>>(
        edge_attr, edge_index, want_ea ? (out + off_ea) : nullptr);
    if (want_ei) eidx_copy_kernel<<<1024, 256>>>(edge_index, out + off_ei);
    colsum_kernel<<<256, 128>>>();
    b1adj_kernel<<<1, 128>>>(W1, b1);

    const int mblocks = (NNODES + 127) / 128;  // 391
    gemm_tc_kernel<256, true, true><<<mblocks, 256>>>(node_attr, s_agg, W1,
                                                      s_b1adj, s_h);
    gemm_tc_kernel<128, false, false><<<mblocks, 256>>>(s_h, nullptr, W2, b2,
                                                        out);
}